// round 13
// baseline (speedup 1.0000x reference)
#include <cuda_runtime.h>
#include <cuda_bf16.h>

// Problem shape (fixed by the dataset)
#define BATCH 128
#define SEQLEN 1024
#define TAG 128
#define MID 512   // fwd: steps 1..512 -> alpha_512 ; bwd: 1023..513 -> beta_512

// Scratch (allocation-free rule: __device__ globals)
__device__ float g_red[BATCH];   // per-batch (logZ - score)

// ---------------- packed f32x2 helpers (Blackwell FFMA2) ----------------
__device__ __forceinline__ unsigned long long pack_f32x2(float lo, float hi) {
    unsigned long long r;
    asm("mov.b64 %0, {%1, %2};" : "=l"(r) : "f"(lo), "f"(hi));
    return r;
}
__device__ __forceinline__ float red_f32x2(unsigned long long v) {
    float lo, hi;
    asm("mov.b64 {%0, %1}, %2;" : "=f"(lo), "=f"(hi) : "l"(v));
    return lo + hi;
}
__device__ __forceinline__ unsigned long long fma2(unsigned long long a,
                                                   unsigned long long b,
                                                   unsigned long long c) {
    unsigned long long d;
    asm("fma.rn.f32x2 %0, %1, %2, %3;" : "=l"(d) : "l"(a), "l"(b), "l"(c));
    return d;
}

// smem geometry (float offsets)
#define VEC_C_OFF   144          // c vector base (alpha at 0); +144 => conflict-free split STS
#define PP_BUF      2064         // per-buffer partial region size
#define PP_B_OFF    1040         // bwd partials offset within buffer (1024+16 bank shift)

// ---------------- one window: fwd step (w+1) + bwd step (1024-w) fused -----
// Every lane spreads BOTH directions (outputs 4*lane..4*lane+3 over own-warp
// 16-u slice) -> two independent fma chains per lane. Combine: lanes 0-15 own
// fwd tags 16w..16w+16, lanes 16-31 own bwd tags (branch-free via selects).
// ONE __syncthreads per window; vector handoff is warp-internal (syncwarp).
template <int SLOT, int BUF, bool RENORM, bool PREP>
__device__ __forceinline__ void step_win(
    int w, int warp, int lane, int dir, int tg,
    float& x, int& kacc,
    float (&eyp)[4], float (&mr)[4],
    const float* __restrict__ ypb, const float* __restrict__ mrow,
    const unsigned long long (&eaf)[32], const unsigned long long (&eab)[32],
    float* __restrict__ vec,      // alpha @0, c @VEC_C_OFF
    float* __restrict__ pp,       // partials: 2 buffers of PP_BUF
    float* __restrict__ sb)       // sb[0]=fwd rep, sb[1]=bwd rep
{
    // renorm factor, fully off the post-barrier chain (sb >=1 window old)
    float K = 1.0f;
    if (RENORM) {
        int kb = (__float_as_int(sb[dir]) >> 23) & 0xff;
        K = __int_as_float((254 - kb) << 23);   // exact 2^(127-kb)
        kacc += 127 - kb;
    }

    // ---- dual spread: 8 independent accumulator chains ----
    unsigned long long af0 = 0ull, af1 = 0ull, af2 = 0ull, af3 = 0ull;
    unsigned long long ab0 = 0ull, ab1 = 0ull, ab2 = 0ull, ab3 = 0ull;
    const ulonglong2* pfv = reinterpret_cast<const ulonglong2*>(vec + 16 * warp);
    const ulonglong2* pbv = reinterpret_cast<const ulonglong2*>(vec + VEC_C_OFF + 16 * warp);
#pragma unroll
    for (int c = 0; c < 4; c++) {
        ulonglong2 vf = pfv[c];
        ulonglong2 vb = pbv[c];
        af0 = fma2(vf.x, eaf[0 * 8 + 2 * c], af0); af0 = fma2(vf.y, eaf[0 * 8 + 2 * c + 1], af0);
        ab0 = fma2(vb.x, eab[0 * 8 + 2 * c], ab0); ab0 = fma2(vb.y, eab[0 * 8 + 2 * c + 1], ab0);
        af1 = fma2(vf.x, eaf[1 * 8 + 2 * c], af1); af1 = fma2(vf.y, eaf[1 * 8 + 2 * c + 1], af1);
        ab1 = fma2(vb.x, eab[1 * 8 + 2 * c], ab1); ab1 = fma2(vb.y, eab[1 * 8 + 2 * c + 1], ab1);
        af2 = fma2(vf.x, eaf[2 * 8 + 2 * c], af2); af2 = fma2(vf.y, eaf[2 * 8 + 2 * c + 1], af2);
        ab2 = fma2(vb.x, eab[2 * 8 + 2 * c], ab2); ab2 = fma2(vb.y, eab[2 * 8 + 2 * c + 1], ab2);
        af3 = fma2(vf.x, eaf[3 * 8 + 2 * c], af3); af3 = fma2(vf.y, eaf[3 * 8 + 2 * c + 1], af3);
        ab3 = fma2(vb.x, eab[3 * 8 + 2 * c], ab3); ab3 = fma2(vb.y, eab[3 * 8 + 2 * c + 1], ab3);
    }
    float* partF = pp + BUF * PP_BUF;
    float* partB = partF + PP_B_OFF;
    float4 qf, qb;
    qf.x = red_f32x2(af0); qf.y = red_f32x2(af1); qf.z = red_f32x2(af2); qf.w = red_f32x2(af3);
    qb.x = red_f32x2(ab0); qb.y = red_f32x2(ab1); qb.z = red_f32x2(ab2); qb.w = red_f32x2(ab3);
    *reinterpret_cast<float4*>(partF + warp * TAG + 4 * lane) = qf;
    *reinterpret_cast<float4*>(partB + warp * TAG + 4 * lane) = qb;

    // prefetch window w+4's (mask, y_pred) for this lane's (dir, tag)
    bool ok = (w <= 507);
    int idx_m = dir ? (1020 - w) : (w + 5);
    int idx_y = dir ? (1019 - w) : (w + 5);
    float m_n = 1.0f, yp_n = 0.0f;
    if (ok) {
        m_n  = __ldg(mrow + idx_m);
        yp_n = __ldg(ypb + (size_t)idx_y * TAG + tg);
    }

    __syncthreads();   // partials ready everywhere

    // ---- combine (branch-free across the two half-warps) ----
    const float* pa = dir ? partB : partF;
    float s = ((pa[tg] + pa[TAG + tg]) + (pa[2 * TAG + tg] + pa[3 * TAG + tg]))
            + ((pa[4 * TAG + tg] + pa[5 * TAG + tg]) + (pa[6 * TAG + tg] + pa[7 * TAG + tg]));
    float F = dir ? 1.0f : eyp[SLOT];       // fwd multiplies ey into s
    float G = dir ? eyp[SLOT] : 1.0f;       // bwd publishes c = beta * ey'
    float sv = (mr[SLOT] > 0.5f) ? s * F : x;
    x = sv * K;
    float pub = x * G;
    (dir ? (vec + VEC_C_OFF) : vec)[tg] = pub;
    if (PREP && tg == 0) sb[dir] = pub;

    float e = __expf(yp_n);
    eyp[SLOT] = ok ? ((dir && w == 507) ? 1.0f : e) : 1.0f;
    mr[SLOT]  = m_n;
    __syncwarp();      // own-slice vector handoff (warp-internal)
}

// ---------------- main kernel: 1 CTA (256 thr) per batch -------------------
__global__ void __launch_bounds__(256, 1)
crf_main_kernel(const float* __restrict__ y_pred,
                const int* __restrict__ y_true32,
                const float* __restrict__ mask,
                const float* __restrict__ A)
{
    const int tid  = threadIdx.x;
    const int warp = tid >> 5;
    const int lane = tid & 31;
    const int dir  = lane >> 4;            // 0 = fwd, 1 = bwd (combine role)
    const int tg   = 16 * warp + (lane & 15);
    const int b    = blockIdx.x;

    __shared__ __align__(16) float s_vec[280];        // alpha[128] @0, c[128] @144
    __shared__ __align__(16) float s_pp[2 * PP_BUF];  // double-buffered partials
    __shared__ float s_sb[2];
    __shared__ int   s_k[2];
    __shared__ float s_logZ;
    __shared__ int   s_is64;

    const float* ypb  = y_pred + (size_t)b * SEQLEN * TAG;
    const float* mrow = mask + (size_t)b * SEQLEN;

    // ---- EA blocks (spread mapping: outputs 4*lane..+3 over u 16*warp..+16)
    unsigned long long eaf[32], eab[32];
    const int u0 = 16 * warp;
    const int T0 = 4 * lane;
#pragma unroll
    for (int j = 0; j < 4; j++)
#pragma unroll
        for (int k = 0; k < 8; k++) {
            float f0 = __expf(__ldg(A + (u0 + 2 * k)     * TAG + (T0 + j)));
            float f1 = __expf(__ldg(A + (u0 + 2 * k + 1) * TAG + (T0 + j)));
            eaf[j * 8 + k] = pack_f32x2(f0, f1);
            float g0 = __expf(__ldg(A + (T0 + j) * TAG + (u0 + 2 * k)));
            float g1 = __expf(__ldg(A + (T0 + j) * TAG + (u0 + 2 * k + 1)));
            eab[j * 8 + k] = pack_f32x2(g0, g1);
        }

    // ---- init state + 4 prefetch slots (per lane's (dir, tag)) ----
    float x;
    float eyp[4], mr[4];
    int kacc = 0;
    if (dir == 0) {
        x = __expf(__ldg(ypb + tg));                 // alpha_0
        s_vec[tg] = x;
        if (tg == 0) s_sb[0] = x;
#pragma unroll
        for (int j = 0; j < 4; j++) {
            eyp[j] = __expf(__ldg(ypb + (1 + j) * TAG + tg));   // ey_{1+j}
            mr[j]  = __ldg(mrow + (1 + j));
        }
    } else {
        x = 1.0f;                                     // beta_1023
        float c0 = __expf(__ldg(ypb + (SEQLEN - 1) * TAG + tg));
        s_vec[VEC_C_OFF + tg] = c0;                   // c_1023 = ey_1023
        if (tg == 0) s_sb[1] = c0;
        mr[0] = 0.0f;  eyp[0] = c0;                   // window 0: masked dummy
        mr[1] = __ldg(mrow + 1023); eyp[1] = __expf(__ldg(ypb + 1022 * TAG + tg));
        mr[2] = __ldg(mrow + 1022); eyp[2] = __expf(__ldg(ypb + 1021 * TAG + tg));
        mr[3] = __ldg(mrow + 1021); eyp[3] = __expf(__ldg(ypb + 1020 * TAG + tg));
    }
    __syncthreads();

    // ---- 512 windows = 128 groups of 4; RENORM slot 0, PREP slot 2 ----
#pragma unroll 1
    for (int g = 0; g < 128; g++) {
        const int w = 4 * g;
        step_win<0, 0, true,  false>(w,     warp, lane, dir, tg, x, kacc, eyp, mr, ypb, mrow, eaf, eab, s_vec, s_pp, s_sb);
        step_win<1, 1, false, false>(w + 1, warp, lane, dir, tg, x, kacc, eyp, mr, ypb, mrow, eaf, eab, s_vec, s_pp, s_sb);
        step_win<2, 0, false, true >(w + 2, warp, lane, dir, tg, x, kacc, eyp, mr, ypb, mrow, eaf, eab, s_vec, s_pp, s_sb);
        step_win<3, 1, false, false>(w + 3, warp, lane, dir, tg, x, kacc, eyp, mr, ypb, mrow, eaf, eab, s_vec, s_pp, s_sb);
    }
    // s_vec[0..128) = alpha_512 (scaled 2^-kf); s_vec[144..272) = beta_512 (2^-kb)

    if (tid == 0)  s_k[0] = kacc;    // warp0 lane0  = fwd
    if (tid == 16) s_k[1] = kacc;    // warp0 lane16 = bwd
    __syncthreads();

    // ---- logZ = log(sum_t alpha[t]*beta[t]) - (kf+kb)*ln2 ----
    if (tid < 32) {
        float v = 0.0f;
#pragma unroll
        for (int j = 0; j < 4; j++) {
            int idx = tid + 32 * j;
            v += s_vec[idx] * s_vec[VEC_C_OFF + idx];
        }
#pragma unroll
        for (int o = 16; o > 0; o >>= 1)
            v += __shfl_xor_sync(0xffffffffu, v, o);
        if (tid == 0)
            s_logZ = logf(v) - (float)(s_k[0] + s_k[1]) * 0.69314718055994530942f;
    }

    // ---- path score (fused) ----
    // y_true is int32 under JAX default x64-disabled; detect genuine LE int64
    // (odd words of first 128 entries all zero <=> int64; tags are 0..127).
    if (tid == 0) s_is64 = 1;
    __syncthreads();
    if (tid < 128 && y_true32[2 * tid + 1] != 0) s_is64 = 0;
    __syncthreads();
    const int stride = s_is64 ? 2 : 1;
    const int* yt = y_true32 + (size_t)b * SEQLEN * stride;

    float acc = 0.0f;
    for (int s = tid; s < SEQLEN; s += 256) {
        int tag = yt[s * stride] & (TAG - 1);
        float m = mrow[s];
        acc += ypb[(size_t)s * TAG + tag] * m;
        if (s + 1 < SEQLEN) {
            int tag2 = yt[(s + 1) * stride] & (TAG - 1);
            acc += A[tag * TAG + tag2] * m * mrow[s + 1];
        }
    }
    float* red = s_pp;   // scratch (scan done)
    red[tid] = acc;
    __syncthreads();
    if (tid < 32) {
        float v = 0.0f;
#pragma unroll
        for (int j = 0; j < 8; j++) v += red[tid + 32 * j];
#pragma unroll
        for (int o = 16; o > 0; o >>= 1)
            v += __shfl_xor_sync(0xffffffffu, v, o);
        if (tid == 0) g_red[b] = s_logZ - v;
    }
}

// ---------------- final mean kernel ----------------
__global__ void __launch_bounds__(128, 1)
crf_final_kernel(float* __restrict__ out)
{
    const int t = threadIdx.x;
    float v = g_red[t];
    __shared__ float red[128];
    red[t] = v;
    __syncthreads();
    if (t < 32) {
        float s = red[t] + red[t + 32] + red[t + 64] + red[t + 96];
#pragma unroll
        for (int o = 16; o > 0; o >>= 1)
            s += __shfl_xor_sync(0xffffffffu, s, o);
        if (t == 0) out[0] = s * (1.0f / (float)BATCH);
    }
}

// ---------------- launch ----------------
extern "C" void kernel_launch(void* const* d_in, const int* in_sizes, int n_in,
                              void* d_out, int out_size)
{
    const float* y_pred = nullptr;
    const float* A = nullptr;
    const int* y_true = nullptr;
    const float* mask = nullptr;
    for (int i = 0; i < n_in; i++) {
        long long sz = in_sizes[i];
        if (sz == (long long)BATCH * SEQLEN * TAG) {
            y_pred = (const float*)d_in[i];
        } else if (sz == (long long)TAG * TAG) {
            A = (const float*)d_in[i];
        } else if (sz == (long long)BATCH * SEQLEN) {
            if (!y_true) y_true = (const int*)d_in[i];
            else mask = (const float*)d_in[i];
        }
    }

    crf_main_kernel<<<BATCH, 256>>>(y_pred, y_true, mask, A);
    crf_final_kernel<<<1, 128>>>((float*)d_out);
}